// round 1
// baseline (speedup 1.0000x reference)
#include <cuda_runtime.h>
#include <cuda_fp16.h>
#include <cstdint>
#include <cstddef>

#define HID   2048
#define NHEAD 16
#define HD    128
#define BATCH 2
#define SEQ   2048
#define MTOT  (BATCH*SEQ)   // 4096

// ---------------- scratch (device globals; no allocation allowed) ----------------
__device__ __half g_xh [MTOT*HID];                 // x in fp16          16.8 MB
__device__ __half g_w  [4][HID*HID];               // Wq,Wk,Wv,Wo fp16   33.6 MB
__device__ __half g_q  [BATCH*NHEAD*SEQ*HD];       // [B,NH,S,D]         16.8 MB
__device__ __half g_k  [BATCH*NHEAD*SEQ*HD];
__device__ __half g_v  [BATCH*NHEAD*SEQ*HD];
__device__ __half g_ctx[MTOT*HID];                 // [M, NH*HD]         16.8 MB

// ---------------- small PTX helpers ----------------
static __device__ __forceinline__ uint32_t smem_u32(const void* p) {
    return (uint32_t)__cvta_generic_to_shared(p);
}
static __device__ __forceinline__ void cp16(uint32_t dst, const void* src) {
    asm volatile("cp.async.cg.shared.global [%0], [%1], 16;\n" :: "r"(dst), "l"(src));
}
static __device__ __forceinline__ void cp_commit() {
    asm volatile("cp.async.commit_group;\n");
}
static __device__ __forceinline__ void cp_wait1() {
    asm volatile("cp.async.wait_group 1;\n");
}
static __device__ __forceinline__ void ldsm_x4(uint32_t* r, uint32_t a) {
    asm volatile("ldmatrix.sync.aligned.m8n8.x4.shared.b16 {%0,%1,%2,%3}, [%4];\n"
        : "=r"(r[0]), "=r"(r[1]), "=r"(r[2]), "=r"(r[3]) : "r"(a));
}
static __device__ __forceinline__ void ldsm_x4t(uint32_t* r, uint32_t a) {
    asm volatile("ldmatrix.sync.aligned.m8n8.x4.trans.shared.b16 {%0,%1,%2,%3}, [%4];\n"
        : "=r"(r[0]), "=r"(r[1]), "=r"(r[2]), "=r"(r[3]) : "r"(a));
}
static __device__ __forceinline__ void mma_f16(float* c, const uint32_t* a, const uint32_t* b) {
    asm volatile(
        "mma.sync.aligned.m16n8k16.row.col.f32.f16.f16.f32 "
        "{%0,%1,%2,%3}, {%4,%5,%6,%7}, {%8,%9}, {%0,%1,%2,%3};\n"
        : "+f"(c[0]), "+f"(c[1]), "+f"(c[2]), "+f"(c[3])
        : "r"(a[0]), "r"(a[1]), "r"(a[2]), "r"(a[3]), "r"(b[0]), "r"(b[1]));
}
static __device__ __forceinline__ uint32_t pack_h2(float a, float b) {
    __half2 h = __floats2half2_rn(a, b);
    return *reinterpret_cast<uint32_t*>(&h);
}

// ---------------- fp32 -> fp16 conversion of x and weights ----------------
__global__ void convert_kernel(const float4* __restrict__ x,
                               const float4* __restrict__ wq,
                               const float4* __restrict__ wk,
                               const float4* __restrict__ wv,
                               const float4* __restrict__ wo)
{
    const int NX = MTOT*HID/4;    // 2,097,152 float4s for x
    const int NW = HID*HID/4;     // 1,048,576 per weight
    int i = blockIdx.x * blockDim.x + threadIdx.x;   // total 6,291,456
    float4 f;
    __half* dst;
    if (i < NX) {
        f = x[i];
        dst = g_xh + (size_t)i * 4;
    } else {
        int j = i - NX;
        int w = j / NW;
        int o = j - w * NW;
        const float4* s = (w == 0) ? wq : (w == 1) ? wk : (w == 2) ? wv : wo;
        f = s[o];
        dst = g_w[w] + (size_t)o * 4;
    }
    __half2* d2 = reinterpret_cast<__half2*>(dst);
    d2[0] = __floats2half2_rn(f.x, f.y);
    d2[1] = __floats2half2_rn(f.z, f.w);
}

// ---------------- GEMM: Y[M,N] = A[M,K] @ W[N,K]^T + bias ----------------
// MODE 0: A = g_xh, W = g_w[blockIdx.z], epilogue -> g_q/g_k/g_v fp16, head-major layout
// MODE 1: A = g_ctx, W = g_w[3],         epilogue -> fp32 out
template<int MODE>
__global__ __launch_bounds__(256)
void gemm_kernel(const float* __restrict__ bias0,
                 const float* __restrict__ bias1,
                 const float* __restrict__ bias2,
                 float* __restrict__ outf)
{
    constexpr int BM = 128, BN = 128, BK = 32, LDS = 40;
    __shared__ __align__(16) __half As[2][BM*LDS];
    __shared__ __align__(16) __half Bs[2][BN*LDS];

    const int m0 = blockIdx.y * BM;
    const int n0 = blockIdx.x * BN;
    const int z  = blockIdx.z;

    const __half* __restrict__ Ain = (MODE == 0) ? g_xh : g_ctx;
    const __half* __restrict__ W   = (MODE == 0) ? (z == 0 ? g_w[0] : z == 1 ? g_w[1] : g_w[2])
                                                 : g_w[3];

    const int tid  = threadIdx.x;
    const int lane = tid & 31;
    const int warp = tid >> 5;
    const int wm = warp >> 1;   // 0..3  (32-row slice)
    const int wn = warp & 1;    // 0..1  (64-col slice)

    float acc[2][8][4];
    #pragma unroll
    for (int i = 0; i < 2; i++)
        #pragma unroll
        for (int j = 0; j < 8; j++)
            #pragma unroll
            for (int k = 0; k < 4; k++) acc[i][j][k] = 0.f;

    auto load_stage = [&](int kt, int st) {
        const int k0 = kt * BK;
        #pragma unroll
        for (int it = 0; it < 2; ++it) {
            int c = tid + it * 256;
            int row = c >> 2, cc = c & 3;
            cp16(smem_u32(&As[st][row*LDS + cc*8]), Ain + (size_t)(m0+row)*HID + k0 + cc*8);
        }
        #pragma unroll
        for (int it = 0; it < 2; ++it) {
            int c = tid + it * 256;
            int row = c >> 2, cc = c & 3;
            cp16(smem_u32(&Bs[st][row*LDS + cc*8]), W + (size_t)(n0+row)*HID + k0 + cc*8);
        }
    };

    load_stage(0, 0);
    cp_commit();

    const int KT = HID / BK;   // 64
    for (int kt = 0; kt < KT; ++kt) {
        const int cur = kt & 1;
        if (kt + 1 < KT) load_stage(kt + 1, cur ^ 1);
        cp_commit();
        cp_wait1();
        __syncthreads();

        #pragma unroll
        for (int kk = 0; kk < 2; ++kk) {
            uint32_t af[2][4];
            #pragma unroll
            for (int mt = 0; mt < 2; ++mt) {
                ldsm_x4(af[mt],
                    smem_u32(&As[cur][(wm*32 + mt*16 + (lane & 15))*LDS + kk*16 + (lane >> 4)*8]));
            }
            #pragma unroll
            for (int np = 0; np < 4; ++np) {
                uint32_t r[4];
                ldsm_x4(r,
                    smem_u32(&Bs[cur][(wn*64 + np*16 + (lane & 15))*LDS + kk*16 + (lane >> 4)*8]));
                uint32_t b0[2] = {r[0], r[2]};
                uint32_t b1[2] = {r[1], r[3]};
                #pragma unroll
                for (int mt = 0; mt < 2; ++mt) {
                    mma_f16(acc[mt][np*2 + 0], af[mt], b0);
                    mma_f16(acc[mt][np*2 + 1], af[mt], b1);
                }
            }
        }
        __syncthreads();
    }

    // ---- epilogue ----
    const float* bias = (MODE == 0) ? (z == 0 ? bias0 : z == 1 ? bias1 : bias2) : bias0;
    __half* dsth = (MODE == 0) ? (z == 0 ? g_q : z == 1 ? g_k : g_v) : (__half*)0;

    #pragma unroll
    for (int mt = 0; mt < 2; ++mt) {
        int r  = wm*32 + mt*16 + (lane >> 2);
        int mg = m0 + r;
        #pragma unroll
        for (int nf = 0; nf < 8; ++nf) {
            int n = n0 + wn*64 + nf*8 + 2*(lane & 3);
            float b0v = bias[n], b1v = bias[n + 1];
            float v00 = acc[mt][nf][0] + b0v, v01 = acc[mt][nf][1] + b1v;
            float v10 = acc[mt][nf][2] + b0v, v11 = acc[mt][nf][3] + b1v;
            if (MODE == 0) {
                int bb = mg >> 11, ss = mg & (SEQ - 1);
                int h = n >> 7, d = n & (HD - 1);
                __half* p = dsth + ((size_t)(bb*NHEAD + h)*SEQ + ss)*HD + d;
                *reinterpret_cast<__half2*>(p)          = __floats2half2_rn(v00, v01);
                *reinterpret_cast<__half2*>(p + 8*HD)   = __floats2half2_rn(v10, v11);
            } else {
                *reinterpret_cast<float2*>(outf + (size_t)mg*HID + n)       = make_float2(v00, v01);
                *reinterpret_cast<float2*>(outf + (size_t)(mg + 8)*HID + n) = make_float2(v10, v11);
            }
        }
    }
}

// ---------------- FlashAttention-2 style kernel ----------------
// grid: (SEQ/128, BATCH*NHEAD); block: 256 threads (8 warps, 16 q-rows each)
__global__ __launch_bounds__(256)
void attn_kernel()
{
    const int bh = blockIdx.y;            // b*16 + h
    const int q0 = blockIdx.x * 128;

    const __half* __restrict__ Qp = g_q + (size_t)bh * SEQ * HD;
    const __half* __restrict__ Kp = g_k + (size_t)bh * SEQ * HD;
    const __half* __restrict__ Vp = g_v + (size_t)bh * SEQ * HD;

    __shared__ __align__(16) __half sm[17408];   // 34.8 KB, reused
    __half* Qs = sm;                 // 128 x 136 (load Q, then reuse)
    __half* Ks = sm;                 //  64 x 136
    __half* Vs = sm + 64*136;        //  64 x 136

    const int tid  = threadIdx.x;
    const int lane = tid & 31;
    const int warp = tid >> 5;

    // ---- load Q tile -> shared (128 rows x 128 d) ----
    #pragma unroll
    for (int it = 0; it < 8; ++it) {
        int c = tid + it * 256;          // 2048 chunks of 8 halves
        int row = c >> 4, cc = c & 15;
        *reinterpret_cast<float4*>(&Qs[row*136 + cc*8]) =
            *reinterpret_cast<const float4*>(Qp + (size_t)(q0 + row)*HD + cc*8);
    }
    __syncthreads();

    // ---- Q fragments in registers: warp owns rows [warp*16, warp*16+16) ----
    uint32_t qf[8][4];
    #pragma unroll
    for (int kf = 0; kf < 8; ++kf) {
        ldsm_x4(qf[kf],
            smem_u32(&Qs[(warp*16 + (lane & 15))*136 + kf*16 + (lane >> 4)*8]));
    }
    // (syncthreads at top of kv loop protects the smem reuse)

    float o[16][4];
    #pragma unroll
    for (int f = 0; f < 16; ++f)
        #pragma unroll
        for (int j = 0; j < 4; ++j) o[f][j] = 0.f;

    float mrow0 = -1e30f, mrow1 = -1e30f;
    float l0 = 0.f, l1 = 0.f;
    const float SC = 0.08838834764831845f;   // 1/sqrt(128)

    for (int t = 0; t < SEQ/64; ++t) {
        __syncthreads();   // previous tile's ldmatrix reads done
        #pragma unroll
        for (int it = 0; it < 4; ++it) {
            int c = tid + it * 256;      // 1024 chunks
            int row = c >> 4, cc = c & 15;
            *reinterpret_cast<float4*>(&Ks[row*136 + cc*8]) =
                *reinterpret_cast<const float4*>(Kp + (size_t)(t*64 + row)*HD + cc*8);
        }
        #pragma unroll
        for (int it = 0; it < 4; ++it) {
            int c = tid + it * 256;
            int row = c >> 4, cc = c & 15;
            *reinterpret_cast<float4*>(&Vs[row*136 + cc*8]) =
                *reinterpret_cast<const float4*>(Vp + (size_t)(t*64 + row)*HD + cc*8);
        }
        __syncthreads();

        // ---- S = Q @ K^T  (16 q-rows x 64 kv) ----
        float s[8][4];
        #pragma unroll
        for (int f = 0; f < 8; ++f)
            #pragma unroll
            for (int j = 0; j < 4; ++j) s[f][j] = 0.f;

        #pragma unroll
        for (int kf = 0; kf < 8; ++kf) {
            #pragma unroll
            for (int np = 0; np < 4; ++np) {
                uint32_t r[4];
                ldsm_x4(r,
                    smem_u32(&Ks[(np*16 + (lane & 15))*136 + kf*16 + (lane >> 4)*8]));
                uint32_t b0[2] = {r[0], r[2]};
                uint32_t b1[2] = {r[1], r[3]};
                mma_f16(s[np*2 + 0], qf[kf], b0);
                mma_f16(s[np*2 + 1], qf[kf], b1);
            }
        }

        // ---- online softmax ----
        float cmax0 = -1e30f, cmax1 = -1e30f;
        #pragma unroll
        for (int f = 0; f < 8; ++f) {
            s[f][0] *= SC; s[f][1] *= SC; s[f][2] *= SC; s[f][3] *= SC;
            cmax0 = fmaxf(cmax0, fmaxf(s[f][0], s[f][1]));
            cmax1 = fmaxf(cmax1, fmaxf(s[f][2], s[f][3]));
        }
        cmax0 = fmaxf(cmax0, __shfl_xor_sync(0xffffffffu, cmax0, 1));
        cmax0 = fmaxf(cmax0, __shfl_xor_sync(0xffffffffu, cmax0, 2));
        cmax1 = fmaxf(cmax1, __shfl_xor_sync(0xffffffffu, cmax1, 1));
        cmax1 = fmaxf(cmax1, __shfl_xor_sync(0xffffffffu, cmax1, 2));

        float mnew0 = fmaxf(mrow0, cmax0);
        float mnew1 = fmaxf(mrow1, cmax1);
        float al0 = __expf(mrow0 - mnew0);
        float al1 = __expf(mrow1 - mnew1);
        mrow0 = mnew0; mrow1 = mnew1;

        float cs0 = 0.f, cs1 = 0.f;
        #pragma unroll
        for (int f = 0; f < 8; ++f) {
            s[f][0] = __expf(s[f][0] - mnew0);
            s[f][1] = __expf(s[f][1] - mnew0);
            s[f][2] = __expf(s[f][2] - mnew1);
            s[f][3] = __expf(s[f][3] - mnew1);
            cs0 += s[f][0] + s[f][1];
            cs1 += s[f][2] + s[f][3];
        }
        cs0 += __shfl_xor_sync(0xffffffffu, cs0, 1);
        cs0 += __shfl_xor_sync(0xffffffffu, cs0, 2);
        cs1 += __shfl_xor_sync(0xffffffffu, cs1, 1);
        cs1 += __shfl_xor_sync(0xffffffffu, cs1, 2);
        l0 = l0 * al0 + cs0;
        l1 = l1 * al1 + cs1;

        #pragma unroll
        for (int f = 0; f < 16; ++f) {
            o[f][0] *= al0; o[f][1] *= al0;
            o[f][2] *= al1; o[f][3] *= al1;
        }

        // ---- P fragments (C-frag -> A-frag identity) ----
        uint32_t pf[4][4];
        #pragma unroll
        for (int kq = 0; kq < 4; ++kq) {
            pf[kq][0] = pack_h2(s[2*kq    ][0], s[2*kq    ][1]);
            pf[kq][1] = pack_h2(s[2*kq    ][2], s[2*kq    ][3]);
            pf[kq][2] = pack_h2(s[2*kq + 1][0], s[2*kq + 1][1]);
            pf[kq][3] = pack_h2(s[2*kq + 1][2], s[2*kq + 1][3]);
        }

        // ---- O += P @ V  (V via ldmatrix.trans) ----
        #pragma unroll
        for (int kq = 0; kq < 4; ++kq) {
            #pragma unroll
            for (int np = 0; np < 8; ++np) {
                uint32_t r[4];
                ldsm_x4t(r,
                    smem_u32(&Vs[(kq*16 + (lane & 15))*136 + np*16 + (lane >> 4)*8]));
                uint32_t b0[2] = {r[0], r[1]};
                uint32_t b1[2] = {r[2], r[3]};
                mma_f16(o[np*2 + 0], pf[kq], b0);
                mma_f16(o[np*2 + 1], pf[kq], b1);
            }
        }
    }

    // ---- normalize and store ctx as [M, NH*HD] fp16 ----
    float inv0 = 1.f / l0;
    float inv1 = 1.f / l1;
    int bb = bh >> 4, h = bh & 15;
    int r = warp*16 + (lane >> 2);
    size_t rowbase = ((size_t)bb*SEQ + q0 + r) * HID + (size_t)h * HD;

    #pragma unroll
    for (int nf = 0; nf < 16; ++nf) {
        int d = nf*8 + 2*(lane & 3);
        *reinterpret_cast<__half2*>(&g_ctx[rowbase + d]) =
            __floats2half2_rn(o[nf][0]*inv0, o[nf][1]*inv0);
        *reinterpret_cast<__half2*>(&g_ctx[rowbase + 8*HID + d]) =
            __floats2half2_rn(o[nf][2]*inv1, o[nf][3]*inv1);
    }
}

// ---------------- launch ----------------
extern "C" void kernel_launch(void* const* d_in, const int* in_sizes, int n_in,
                              void* d_out, int out_size)
{
    const float* x  = (const float*)d_in[0];
    const float* Wq = (const float*)d_in[1];
    const float* bq = (const float*)d_in[2];
    const float* Wk = (const float*)d_in[3];
    const float* bk = (const float*)d_in[4];
    const float* Wv = (const float*)d_in[5];
    const float* bv = (const float*)d_in[6];
    const float* Wo = (const float*)d_in[7];
    const float* bo = (const float*)d_in[8];

    convert_kernel<<<24576, 256>>>((const float4*)x, (const float4*)Wq,
                                   (const float4*)Wk, (const float4*)Wv,
                                   (const float4*)Wo);

    gemm_kernel<0><<<dim3(16, 32, 3), 256>>>(bq, bk, bv, nullptr);

    attn_kernel<<<dim3(16, 32), 256>>>();

    gemm_kernel<1><<<dim3(16, 32, 1), 256>>>(bo, nullptr, nullptr, (float*)d_out);
}

// round 5
// speedup vs baseline: 1.0180x; 1.0180x over previous
#include <cuda_runtime.h>
#include <cuda_fp16.h>
#include <cstdint>
#include <cstddef>

#define HID   2048
#define NHEAD 16
#define HD    128
#define BATCH 2
#define SEQ   2048
#define MTOT  (BATCH*SEQ)   // 4096

// ---------------- scratch (device globals; no allocation allowed) ----------------
__device__ __half g_xh [MTOT*HID];                 // x in fp16
__device__ __half g_w  [4][HID*HID];               // Wq,Wk,Wv,Wo fp16
__device__ __half g_q  [BATCH*NHEAD*SEQ*HD];       // [B,NH,S,D]
__device__ __half g_k  [BATCH*NHEAD*SEQ*HD];
__device__ __half g_v  [BATCH*NHEAD*SEQ*HD];
__device__ __half g_ctx[MTOT*HID];                 // [M, NH*HD]

// ---------------- PTX helpers (baseline ISA only: sm_80/75 features) ----------------
static __device__ __forceinline__ uint32_t smem_u32(const void* p) {
    return (uint32_t)__cvta_generic_to_shared(p);
}
static __device__ __forceinline__ void cp16(uint32_t dst, const void* src) {
    asm volatile("cp.async.cg.shared.global [%0], [%1], 16;\n" :: "r"(dst), "l"(src));
}
static __device__ __forceinline__ void cp_commit() {
    asm volatile("cp.async.commit_group;\n");
}
template<int N>
static __device__ __forceinline__ void cp_wait_group() {
    asm volatile("cp.async.wait_group %0;\n" :: "n"(N));
}
static __device__ __forceinline__ void ldsm_x4(uint32_t* r, uint32_t a) {
    asm volatile("ldmatrix.sync.aligned.m8n8.x4.shared.b16 {%0,%1,%2,%3}, [%4];\n"
        : "=r"(r[0]), "=r"(r[1]), "=r"(r[2]), "=r"(r[3]) : "r"(a));
}
static __device__ __forceinline__ void ldsm_x4t(uint32_t* r, uint32_t a) {
    asm volatile("ldmatrix.sync.aligned.m8n8.x4.trans.shared.b16 {%0,%1,%2,%3}, [%4];\n"
        : "=r"(r[0]), "=r"(r[1]), "=r"(r[2]), "=r"(r[3]) : "r"(a));
}
static __device__ __forceinline__ void mma_f16(float* c, const uint32_t* a, const uint32_t* b) {
    asm volatile(
        "mma.sync.aligned.m16n8k16.row.col.f32.f16.f16.f32 "
        "{%0,%1,%2,%3}, {%4,%5,%6,%7}, {%8,%9}, {%0,%1,%2,%3};\n"
        : "+f"(c[0]), "+f"(c[1]), "+f"(c[2]), "+f"(c[3])
        : "r"(a[0]), "r"(a[1]), "r"(a[2]), "r"(a[3]), "r"(b[0]), "r"(b[1]));
}
static __device__ __forceinline__ uint32_t pack_h2(float a, float b) {
    __half2 h = __floats2half2_rn(a, b);
    return *reinterpret_cast<uint32_t*>(&h);
}

// ---------------- fp32 -> fp16 conversion of x and weights ----------------
__global__ void convert_kernel(const float4* __restrict__ x,
                               const float4* __restrict__ wq,
                               const float4* __restrict__ wk,
                               const float4* __restrict__ wv,
                               const float4* __restrict__ wo)
{
    const int NX = MTOT*HID/4;
    const int NW = HID*HID/4;
    int i = blockIdx.x * blockDim.x + threadIdx.x;
    float4 f;
    __half* dst;
    if (i < NX) {
        f = x[i];
        dst = g_xh + (size_t)i * 4;
    } else {
        int j = i - NX;
        int w = j / NW;
        int o = j - w * NW;
        const float4* s = (w == 0) ? wq : (w == 1) ? wk : (w == 2) ? wv : wo;
        f = s[o];
        dst = g_w[w] + (size_t)o * 4;
    }
    __half2* d2 = reinterpret_cast<__half2*>(dst);
    d2[0] = __floats2half2_rn(f.x, f.y);
    d2[1] = __floats2half2_rn(f.z, f.w);
}

// =====================================================================
// HMMA GEMM v2:  Y[M,N] = A[M,K] @ W[N,K]^T + bias
// Block tile 256(M) x 128(N), BK=32, 4-stage cp.async pipeline.
// 8 warps, each computes a 64x64 warp tile (16 MAC per ldsm byte ->
// smem crossbar demand ~64 B/cyc/SM, below the 128 B/cyc cap).
// MODE 0: A = g_xh, W = g_w[z], out -> g_q/g_k/g_v fp16 head-major + bias
// MODE 1: A = g_ctx, W = g_w[3], out -> fp32 d_out + bias
// =====================================================================
#define BM      256
#define BN      128
#define BK      32
#define NSTG    4
#define LDSH    40                       // padded row length in halves (80B rows)
#define A_HALVES (BM*LDSH)               // 10240 halves = 20480 B
#define B_HALVES (BN*LDSH)               //  5120 halves = 10240 B
#define STG_HALVES (A_HALVES + B_HALVES) // 15360 halves = 30720 B
#define KT_ITERS (HID/BK)                // 64

template<int MODE>
__global__ __launch_bounds__(256, 1)
void gemm_kernel(const float* __restrict__ bias0,
                 const float* __restrict__ bias1,
                 const float* __restrict__ bias2,
                 float* __restrict__ outf)
{
    extern __shared__ __align__(16) __half gsm[];

    const int m0 = blockIdx.y * BM;
    const int n0 = blockIdx.x * BN;
    const int z  = blockIdx.z;

    const __half* __restrict__ Ain = (MODE == 0) ? g_xh : g_ctx;
    const __half* __restrict__ W   = (MODE == 0) ? (z == 0 ? g_w[0] : z == 1 ? g_w[1] : g_w[2])
                                                 : g_w[3];

    const int tid  = threadIdx.x;
    const int lane = tid & 31;
    const int warp = tid >> 5;
    const int wm = warp >> 1;   // 0..3  (64-row slice)
    const int wn = warp & 1;    // 0..1  (64-col slice)

    float acc[4][8][4];
    #pragma unroll
    for (int i = 0; i < 4; i++)
        #pragma unroll
        for (int j = 0; j < 8; j++)
            #pragma unroll
            for (int k = 0; k < 4; k++) acc[i][j][k] = 0.f;

    // ---- stage loader: K-block kb into stage st ----
    auto load_stage = [&](int st, int kb) {
        __half* As = gsm + st * STG_HALVES;
        __half* Bs = As + A_HALVES;
        const __half* Aptr = Ain + (size_t)m0 * HID + kb * BK;
        const __half* Bptr = W   + (size_t)n0 * HID + kb * BK;
        #pragma unroll
        for (int it = 0; it < 4; ++it) {          // A: 1024 16B chunks
            int c = tid + it * 256;
            int row = c >> 2, cc = c & 3;
            cp16(smem_u32(As + row * LDSH + cc * 8), Aptr + (size_t)row * HID + cc * 8);
        }
        #pragma unroll
        for (int it = 0; it < 2; ++it) {          // B: 512 16B chunks
            int c = tid + it * 256;
            int row = c >> 2, cc = c & 3;
            cp16(smem_u32(Bs + row * LDSH + cc * 8), Bptr + (size_t)row * HID + cc * 8);
        }
    };

    // prologue: blocks 0,1,2 -> stages 0,1,2
    #pragma unroll
    for (int b = 0; b < NSTG - 1; ++b) {
        load_stage(b, b);
        cp_commit();
    }

    // ---- main K loop ----
    for (int kt = 0; kt < KT_ITERS; ++kt) {
        const int s = kt & (NSTG - 1);
        cp_wait_group<2>();     // block kt resident
        __syncthreads();        // all warps done with stage (kt-1)&3; data visible

        // prefetch block kt+3 into stage (kt+3)&3 == (kt-1)&3 (safe after sync)
        const int pf = kt + NSTG - 1;
        if (pf < KT_ITERS) load_stage(pf & (NSTG - 1), pf);
        cp_commit();            // empty group OK when pf out of range

        const __half* As = gsm + s * STG_HALVES;
        const __half* Bs = As + A_HALVES;

        #pragma unroll
        for (int kk = 0; kk < 2; ++kk) {
            uint32_t af[4][4];
            #pragma unroll
            for (int mt = 0; mt < 4; ++mt) {
                ldsm_x4(af[mt],
                    smem_u32(As + (wm*64 + mt*16 + (lane & 15)) * LDSH
                                + kk*16 + (lane >> 4) * 8));
            }
            #pragma unroll
            for (int np = 0; np < 4; ++np) {
                uint32_t r[4];
                ldsm_x4(r,
                    smem_u32(Bs + (wn*64 + np*16 + (lane & 15)) * LDSH
                                + kk*16 + (lane >> 4) * 8));
                uint32_t b0[2] = {r[0], r[2]};
                uint32_t b1[2] = {r[1], r[3]};
                #pragma unroll
                for (int mt = 0; mt < 4; ++mt) {
                    mma_f16(acc[mt][np*2 + 0], af[mt], b0);
                    mma_f16(acc[mt][np*2 + 1], af[mt], b1);
                }
            }
        }
    }

    // ---- epilogue ----
    const float* bias = (MODE == 0) ? (z == 0 ? bias0 : z == 1 ? bias1 : bias2) : bias0;
    __half* dsth = (MODE == 0) ? (z == 0 ? g_q : z == 1 ? g_k : g_v) : (__half*)0;

    #pragma unroll
    for (int mt = 0; mt < 4; ++mt) {
        int r  = wm*64 + mt*16 + (lane >> 2);
        int mg = m0 + r;
        #pragma unroll
        for (int nf = 0; nf < 8; ++nf) {
            int n = n0 + wn*64 + nf*8 + 2*(lane & 3);
            float b0v = bias[n], b1v = bias[n + 1];
            float v00 = acc[mt][nf][0] + b0v, v01 = acc[mt][nf][1] + b1v;
            float v10 = acc[mt][nf][2] + b0v, v11 = acc[mt][nf][3] + b1v;
            if (MODE == 0) {
                int bb = mg >> 11, ss = mg & (SEQ - 1);
                int h = n >> 7, d = n & (HD - 1);
                __half* p = dsth + ((size_t)(bb*NHEAD + h)*SEQ + ss)*HD + d;
                *reinterpret_cast<__half2*>(p)        = __floats2half2_rn(v00, v01);
                *reinterpret_cast<__half2*>(p + 8*HD) = __floats2half2_rn(v10, v11);
            } else {
                *reinterpret_cast<float2*>(outf + (size_t)mg*HID + n)       = make_float2(v00, v01);
                *reinterpret_cast<float2*>(outf + (size_t)(mg + 8)*HID + n) = make_float2(v10, v11);
            }
        }
    }
}

// =====================================================================
// FlashAttention-2 kernel with 2-stage cp.async K/V pipeline.
// grid: (SEQ/128, BATCH*NHEAD); block: 256 threads (8 warps, 16 q-rows each)
// dyn smem: 2 stages x (K 64x136 + V 64x136) + Q 128x136  (halves)
// =====================================================================
#define ATT_STG_H   (2*64*136)        // 17408 halves per stage (K+V)
#define ATT_Q_H     (128*136)         // 17408 halves
#define ATT_SMEM_B  ((2*ATT_STG_H + ATT_Q_H) * 2)   // 104448 bytes

__global__ __launch_bounds__(256, 1)
void attn_kernel()
{
    extern __shared__ __align__(16) __half asm_sm[];

    const int bh = blockIdx.y;
    const int q0 = blockIdx.x * 128;

    const __half* __restrict__ Qp = g_q + (size_t)bh * SEQ * HD;
    const __half* __restrict__ Kp = g_k + (size_t)bh * SEQ * HD;
    const __half* __restrict__ Vp = g_v + (size_t)bh * SEQ * HD;

    __half* Qs = asm_sm + 2 * ATT_STG_H;

    const int tid  = threadIdx.x;
    const int lane = tid & 31;
    const int warp = tid >> 5;

    // ---- stage loader: kv tile t into stage st ----
    auto load_kv = [&](int st, int t) {
        __half* Ks = asm_sm + st * ATT_STG_H;
        __half* Vs = Ks + 64*136;
        #pragma unroll
        for (int it = 0; it < 4; ++it) {      // K: 1024 chunks
            int c = tid + it * 256;
            int row = c >> 4, cc = c & 15;
            cp16(smem_u32(Ks + row*136 + cc*8), Kp + (size_t)(t*64 + row)*HD + cc*8);
        }
        #pragma unroll
        for (int it = 0; it < 4; ++it) {      // V: 1024 chunks
            int c = tid + it * 256;
            int row = c >> 4, cc = c & 15;
            cp16(smem_u32(Vs + row*136 + cc*8), Vp + (size_t)(t*64 + row)*HD + cc*8);
        }
    };

    // ---- prologue: Q (group 0), KV tile 0 (group 1) ----
    #pragma unroll
    for (int it = 0; it < 8; ++it) {
        int c = tid + it * 256;
        int row = c >> 4, cc = c & 15;
        cp16(smem_u32(Qs + row*136 + cc*8), Qp + (size_t)(q0 + row)*HD + cc*8);
    }
    cp_commit();
    load_kv(0, 0);
    cp_commit();

    cp_wait_group<1>();   // Q resident
    __syncthreads();

    uint32_t qf[8][4];
    #pragma unroll
    for (int kf = 0; kf < 8; ++kf) {
        ldsm_x4(qf[kf],
            smem_u32(Qs + (warp*16 + (lane & 15))*136 + kf*16 + (lane >> 4)*8));
    }

    float o[16][4];
    #pragma unroll
    for (int f = 0; f < 16; ++f)
        #pragma unroll
        for (int j = 0; j < 4; ++j) o[f][j] = 0.f;

    float mrow0 = -1e30f, mrow1 = -1e30f;
    float l0 = 0.f, l1 = 0.f;
    const float SC = 0.08838834764831845f;   // 1/sqrt(128)

    for (int t = 0; t < SEQ/64; ++t) {
        const int cur = t & 1;
        cp_wait_group<0>();   // KV tile t resident
        __syncthreads();      // all warps done computing tile t-1; data visible

        // prefetch tile t+1 into the other stage (its readers drained by sync)
        if (t + 1 < SEQ/64) load_kv(cur ^ 1, t + 1);
        cp_commit();

        const __half* Ks = asm_sm + cur * ATT_STG_H;
        const __half* Vs = Ks + 64*136;

        // ---- S = Q @ K^T ----
        float s[8][4];
        #pragma unroll
        for (int f = 0; f < 8; ++f)
            #pragma unroll
            for (int j = 0; j < 4; ++j) s[f][j] = 0.f;

        #pragma unroll
        for (int kf = 0; kf < 8; ++kf) {
            #pragma unroll
            for (int np = 0; np < 4; ++np) {
                uint32_t r[4];
                ldsm_x4(r,
                    smem_u32(Ks + (np*16 + (lane & 15))*136 + kf*16 + (lane >> 4)*8));
                uint32_t b0[2] = {r[0], r[2]};
                uint32_t b1[2] = {r[1], r[3]};
                mma_f16(s[np*2 + 0], qf[kf], b0);
                mma_f16(s[np*2 + 1], qf[kf], b1);
            }
        }

        // ---- online softmax ----
        float cmax0 = -1e30f, cmax1 = -1e30f;
        #pragma unroll
        for (int f = 0; f < 8; ++f) {
            s[f][0] *= SC; s[f][1] *= SC; s[f][2] *= SC; s[f][3] *= SC;
            cmax0 = fmaxf(cmax0, fmaxf(s[f][0], s[f][1]));
            cmax1 = fmaxf(cmax1, fmaxf(s[f][2], s[f][3]));
        }
        cmax0 = fmaxf(cmax0, __shfl_xor_sync(0xffffffffu, cmax0, 1));
        cmax0 = fmaxf(cmax0, __shfl_xor_sync(0xffffffffu, cmax0, 2));
        cmax1 = fmaxf(cmax1, __shfl_xor_sync(0xffffffffu, cmax1, 1));
        cmax1 = fmaxf(cmax1, __shfl_xor_sync(0xffffffffu, cmax1, 2));

        float mnew0 = fmaxf(mrow0, cmax0);
        float mnew1 = fmaxf(mrow1, cmax1);
        float al0 = __expf(mrow0 - mnew0);
        float al1 = __expf(mrow1 - mnew1);
        mrow0 = mnew0; mrow1 = mnew1;

        float cs0 = 0.f, cs1 = 0.f;
        #pragma unroll
        for (int f = 0; f < 8; ++f) {
            s[f][0] = __expf(s[f][0] - mnew0);
            s[f][1] = __expf(s[f][1] - mnew0);
            s[f][2] = __expf(s[f][2] - mnew1);
            s[f][3] = __expf(s[f][3] - mnew1);
            cs0 += s[f][0] + s[f][1];
            cs1 += s[f][2] + s[f][3];
        }
        cs0 += __shfl_xor_sync(0xffffffffu, cs0, 1);
        cs0 += __shfl_xor_sync(0xffffffffu, cs0, 2);
        cs1 += __shfl_xor_sync(0xffffffffu, cs1, 1);
        cs1 += __shfl_xor_sync(0xffffffffu, cs1, 2);
        l0 = l0 * al0 + cs0;
        l1 = l1 * al1 + cs1;

        #pragma unroll
        for (int f = 0; f < 16; ++f) {
            o[f][0] *= al0; o[f][1] *= al0;
            o[f][2] *= al1; o[f][3] *= al1;
        }

        // ---- P fragments ----
        uint32_t pf[4][4];
        #pragma unroll
        for (int kq = 0; kq < 4; ++kq) {
            pf[kq][0] = pack_h2(s[2*kq    ][0], s[2*kq    ][1]);
            pf[kq][1] = pack_h2(s[2*kq    ][2], s[2*kq    ][3]);
            pf[kq][2] = pack_h2(s[2*kq + 1][0], s[2*kq + 1][1]);
            pf[kq][3] = pack_h2(s[2*kq + 1][2], s[2*kq + 1][3]);
        }

        // ---- O += P @ V ----
        #pragma unroll
        for (int kq = 0; kq < 4; ++kq) {
            #pragma unroll
            for (int np = 0; np < 8; ++np) {
                uint32_t r[4];
                ldsm_x4t(r,
                    smem_u32(Vs + (kq*16 + (lane & 15))*136 + np*16 + (lane >> 4)*8));
                uint32_t b0[2] = {r[0], r[1]};
                uint32_t b1[2] = {r[2], r[3]};
                mma_f16(o[np*2 + 0], pf[kq], b0);
                mma_f16(o[np*2 + 1], pf[kq], b1);
            }
        }
    }

    // ---- normalize and store ctx as [M, NH*HD] fp16 ----
    float inv0 = 1.f / l0;
    float inv1 = 1.f / l1;
    int bb = bh >> 4, h = bh & 15;
    int r = warp*16 + (lane >> 2);
    size_t rowbase = ((size_t)bb*SEQ + q0 + r) * HID + (size_t)h * HD;

    #pragma unroll
    for (int nf = 0; nf < 16; ++nf) {
        int d = nf*8 + 2*(lane & 3);
        *reinterpret_cast<__half2*>(&g_ctx[rowbase + d]) =
            __floats2half2_rn(o[nf][0]*inv0, o[nf][1]*inv0);
        *reinterpret_cast<__half2*>(&g_ctx[rowbase + 8*HID + d]) =
            __floats2half2_rn(o[nf][2]*inv1, o[nf][3]*inv1);
    }
}

// ---------------- launch ----------------
extern "C" void kernel_launch(void* const* d_in, const int* in_sizes, int n_in,
                              void* d_out, int out_size)
{
    const float* x  = (const float*)d_in[0];
    const float* Wq = (const float*)d_in[1];
    const float* bq = (const float*)d_in[2];
    const float* Wk = (const float*)d_in[3];
    const float* bk = (const float*)d_in[4];
    const float* Wv = (const float*)d_in[5];
    const float* bv = (const float*)d_in[6];
    const float* Wo = (const float*)d_in[7];
    const float* bo = (const float*)d_in[8];

    const int gemm_smem = NSTG * STG_HALVES * 2;   // 122880 B
    // Unconditional each call (no static guards — determinism rule).
    cudaFuncSetAttribute(gemm_kernel<0>,
                         cudaFuncAttributeMaxDynamicSharedMemorySize, gemm_smem);
    cudaFuncSetAttribute(gemm_kernel<1>,
                         cudaFuncAttributeMaxDynamicSharedMemorySize, gemm_smem);
    cudaFuncSetAttribute(attn_kernel,
                         cudaFuncAttributeMaxDynamicSharedMemorySize, ATT_SMEM_B);

    convert_kernel<<<24576, 256>>>((const float4*)x, (const float4*)Wq,
                                   (const float4*)Wk, (const float4*)Wv,
                                   (const float4*)Wo);

    gemm_kernel<0><<<dim3(HID/BN, MTOT/BM, 3), 256, gemm_smem>>>(bq, bk, bv, nullptr);

    attn_kernel<<<dim3(16, 32), 256, ATT_SMEM_B>>>();

    gemm_kernel<1><<<dim3(HID/BN, MTOT/BM, 1), 256, gemm_smem>>>(bo, nullptr, nullptr,
                                                                 (float*)d_out);
}